// round 1
// baseline (speedup 1.0000x reference)
#include <cuda_runtime.h>
#include <math.h>

#define BB 4
#define CC 256
#define HH 8
#define NN 2048
#define NJ 6144        // 3*NN
#define KF 96          // Ch*3 per head
#define ROWS 768       // C*3 rows per batch
#define ZSTR 65        // padded stride for zs/ps (bank-conflict-free)

// Scratch: q/k/z projections and attention output, layout [b][e*3+d][n]
// (per-head view: [b][h][96][n], contiguous along n)
__device__ float g_q[BB * ROWS * NN];
__device__ float g_k[BB * ROWS * NN];
__device__ float g_z[BB * ROWS * NN];
__device__ float g_o[BB * ROWS * NN];

// ---------------------------------------------------------------------------
// Projection: Y[b][e][j] = sum_c W[c][e] * X[b][c][j] + eps*b[e,d]/||b[e,:]||
// X layout [B][C][3*N] (j = d*N + n). 64x64 tile, K-chunks of 16, 4x4/thread.
// ---------------------------------------------------------------------------
__global__ __launch_bounds__(256) void proj_kernel(
    const float* __restrict__ X, const float* __restrict__ W,
    const float* __restrict__ bias, float* __restrict__ Y) {
    __shared__ float As[16][64];
    __shared__ float Xs[16][64];
    const int tid = threadIdx.x;
    const int tx = tid & 15, ty = tid >> 4;
    const int j0 = blockIdx.x * 64;
    const int e0 = blockIdx.y * 64;
    const size_t xoff = (size_t)blockIdx.z * CC * NJ;

    float acc[4][4] = {};
    for (int c0 = 0; c0 < CC; c0 += 16) {
#pragma unroll
        for (int i = 0; i < 4; i++) {
            int idx = tid + i * 256;
            int kk = idx >> 6, l = idx & 63;
            As[kk][l] = W[(size_t)(c0 + kk) * CC + e0 + l];
            Xs[kk][l] = X[xoff + (size_t)(c0 + kk) * NJ + j0 + l];
        }
        __syncthreads();
#pragma unroll
        for (int kk = 0; kk < 16; kk++) {
            float4 a4 = *(const float4*)&As[kk][ty * 4];
            float4 x4 = *(const float4*)&Xs[kk][tx * 4];
            float av[4] = {a4.x, a4.y, a4.z, a4.w};
            float xv[4] = {x4.x, x4.y, x4.z, x4.w};
#pragma unroll
            for (int i = 0; i < 4; i++)
#pragma unroll
                for (int j = 0; j < 4; j++)
                    acc[i][j] = fmaf(av[i], xv[j], acc[i][j]);
        }
        __syncthreads();
    }

    const int d = j0 >> 11;  // 64-wide j-tiles never cross a d boundary
#pragma unroll
    for (int i = 0; i < 4; i++) {
        int e = e0 + ty * 4 + i;
        float b0 = bias[e * 3 + 0], b1 = bias[e * 3 + 1], b2 = bias[e * 3 + 2];
        float u = 1e-6f * bias[e * 3 + d] * rsqrtf(b0 * b0 + b1 * b1 + b2 * b2);
#pragma unroll
        for (int j = 0; j < 4; j++)
            Y[xoff + (size_t)e * NJ + j0 + tx * 4 + j] = acc[i][j] + u;
    }
}

// ---------------------------------------------------------------------------
// Fused flash attention (fp32, online softmax).
// Per block: one (b, h, 64-row m-tile). Loops 32 n-tiles of 64.
//   S[64x64]   = q[96 x 64m]^T k[96 x 64n], scaled 1/sqrt(96)
//   P = online-softmax(S);  O[64m x 96] += P @ z[96 x 64n]^T
// ---------------------------------------------------------------------------
__global__ __launch_bounds__(256, 2) void flash_kernel() {
    extern __shared__ float sm[];
    float* qs = sm;                      // [96][64]
    float* ks = sm + KF * 64;            // [96][64]
    float* zs = sm + 2 * KF * 64;        // [96][ZSTR]
    float* ps = zs + KF * ZSTR;          // [64][ZSTR]

    const int tid = threadIdx.x;
    const int tx = tid & 15, ty = tid >> 4;
    const int m0 = blockIdx.x * 64;
    const size_t base = ((size_t)blockIdx.z * ROWS + (size_t)blockIdx.y * KF) * NN;
    const float* qg = g_q + base;
    const float* kg = g_k + base;
    const float* zg = g_z + base;

#pragma unroll 8
    for (int i = 0; i < 24; i++) {
        int idx = tid + i * 256;
        int k = idx >> 6, l = idx & 63;
        qs[k * 64 + l] = qg[(size_t)k * NN + m0 + l];
    }

    float o[4][6] = {};
    float mr[4], lr[4];
#pragma unroll
    for (int i = 0; i < 4; i++) { mr[i] = -INFINITY; lr[i] = 0.f; }

    // scale * log2(e): exp(scale*x) == exp2(C2*x)
    const float C2 = 0.10206207261596577f * 1.4426950408889634f;

    for (int nt = 0; nt < 32; nt++) {
        __syncthreads();  // previous PZ done before overwriting ks/zs (also covers qs)
        const int n0 = nt * 64;
#pragma unroll 8
        for (int i = 0; i < 24; i++) {
            int idx = tid + i * 256;
            int k = idx >> 6, l = idx & 63;
            ks[k * 64 + l]   = kg[(size_t)k * NN + n0 + l];
            zs[k * ZSTR + l] = zg[(size_t)k * NN + n0 + l];
        }
        __syncthreads();

        // --- S = q^T k ---
        float s[4][4] = {};
#pragma unroll 8
        for (int k = 0; k < KF; k++) {
            float4 q4 = *(const float4*)&qs[k * 64 + ty * 4];
            float4 k4 = *(const float4*)&ks[k * 64 + tx * 4];
            float qa[4] = {q4.x, q4.y, q4.z, q4.w};
            float ka[4] = {k4.x, k4.y, k4.z, k4.w};
#pragma unroll
            for (int i = 0; i < 4; i++)
#pragma unroll
                for (int j = 0; j < 4; j++)
                    s[i][j] = fmaf(qa[i], ka[j], s[i][j]);
        }

        // --- online softmax (row groups = 16 lanes sharing ty) ---
#pragma unroll
        for (int i = 0; i < 4; i++) {
            float rm = fmaxf(fmaxf(s[i][0], s[i][1]), fmaxf(s[i][2], s[i][3]));
            rm = fmaxf(rm, __shfl_xor_sync(0xffffffffu, rm, 1));
            rm = fmaxf(rm, __shfl_xor_sync(0xffffffffu, rm, 2));
            rm = fmaxf(rm, __shfl_xor_sync(0xffffffffu, rm, 4));
            rm = fmaxf(rm, __shfl_xor_sync(0xffffffffu, rm, 8));
            float mn = fmaxf(mr[i], rm);
            float corr = exp2f((mr[i] - mn) * C2);
            mr[i] = mn;
            float rs = 0.f;
#pragma unroll
            for (int j = 0; j < 4; j++) {
                s[i][j] = exp2f((s[i][j] - mn) * C2);
                rs += s[i][j];
            }
            rs += __shfl_xor_sync(0xffffffffu, rs, 1);
            rs += __shfl_xor_sync(0xffffffffu, rs, 2);
            rs += __shfl_xor_sync(0xffffffffu, rs, 4);
            rs += __shfl_xor_sync(0xffffffffu, rs, 8);
            lr[i] = lr[i] * corr + rs;
#pragma unroll
            for (int j = 0; j < 6; j++) o[i][j] *= corr;
        }

#pragma unroll
        for (int i = 0; i < 4; i++)
#pragma unroll
            for (int j = 0; j < 4; j++)
                ps[(ty * 4 + i) * ZSTR + tx * 4 + j] = s[i][j];
        __syncthreads();

        // --- O += P @ z^T ---
#pragma unroll 4
        for (int n = 0; n < 64; n++) {
            float pm[4], zk[6];
#pragma unroll
            for (int i = 0; i < 4; i++) pm[i] = ps[(ty * 4 + i) * ZSTR + n];
#pragma unroll
            for (int j = 0; j < 6; j++) zk[j] = zs[(tx * 6 + j) * ZSTR + n];
#pragma unroll
            for (int i = 0; i < 4; i++)
#pragma unroll
                for (int j = 0; j < 6; j++)
                    o[i][j] = fmaf(pm[i], zk[j], o[i][j]);
        }
    }

    // epilogue: normalize and write [b][h*96 + k'][m]
    float* og = g_o + base;
#pragma unroll
    for (int i = 0; i < 4; i++) {
        float inv = 1.f / lr[i];
#pragma unroll
        for (int j = 0; j < 6; j++)
            og[(size_t)(tx * 6 + j) * NN + m0 + ty * 4 + i] = o[i][j] * inv;
    }
}

// ---------------------------------------------------------------------------
extern "C" void kernel_launch(void* const* d_in, const int* in_sizes, int n_in,
                              void* d_out, int out_size) {
    const float* Q  = (const float*)d_in[0];
    const float* K  = (const float*)d_in[1];
    const float* Z  = (const float*)d_in[2];
    const float* Wq = (const float*)d_in[3];
    const float* bq = (const float*)d_in[4];
    const float* Wk = (const float*)d_in[5];
    const float* bk = (const float*)d_in[6];
    const float* Wz = (const float*)d_in[7];
    const float* bz = (const float*)d_in[8];
    const float* Wo = (const float*)d_in[9];
    const float* bo = (const float*)d_in[10];
    float* out = (float*)d_out;

    float *pq, *pk, *pz, *po;
    cudaGetSymbolAddress((void**)&pq, g_q);
    cudaGetSymbolAddress((void**)&pk, g_k);
    cudaGetSymbolAddress((void**)&pz, g_z);
    cudaGetSymbolAddress((void**)&po, g_o);

    const int FLASH_SMEM = (2 * KF * 64 + KF * ZSTR + 64 * ZSTR) * 4;  // 90752 B
    cudaFuncSetAttribute(flash_kernel,
                         cudaFuncAttributeMaxDynamicSharedMemorySize, FLASH_SMEM);

    dim3 blk(256);
    dim3 gproj(NJ / 64, CC / 64, BB);   // 96 x 4 x 4
    proj_kernel<<<gproj, blk>>>(Q, Wq, bq, pq);
    proj_kernel<<<gproj, blk>>>(K, Wk, bk, pk);
    proj_kernel<<<gproj, blk>>>(Z, Wz, bz, pz);

    flash_kernel<<<dim3(NN / 64, HH, BB), blk, FLASH_SMEM>>>();

    proj_kernel<<<gproj, blk>>>(po, Wo, bo, out);
}

// round 3
// speedup vs baseline: 1.7465x; 1.7465x over previous
#include <cuda_runtime.h>
#include <math.h>
#include <stdint.h>

#define BB 4
#define CC 256
#define HH 8
#define NN 2048
#define NJ 6144        // 3*NN
#define KF 96          // Ch*3 per head
#define ROWS 768       // C*3 rows per batch

// flash tiling
#define MT 128         // m rows per block (8 warps x 16)
#define NT 64          // n per iteration
#define KSTR 100       // ks stride: [n][k], conflict-free B-frag loads
#define ZSTR2 68       // zs stride: [k'][n]
#define PSTR 68        // per-warp P stage stride
#define QSTR 132       // q staging stride (prologue only)

// smem (floats): ks[64*100]=6400 | zs[96*68]=6528 | pstage[8*16*68]=8704
#define KS_OFF 0
#define ZS_OFF 6400
#define PS_OFF 12928
#define SMEM_FLOATS 21632   // 86528 bytes; q staging (96*132=12672) aliases front

__device__ float g_q[BB * ROWS * NN];
__device__ float g_k[BB * ROWS * NN];
__device__ float g_z[BB * ROWS * NN];
__device__ float g_o[BB * ROWS * NN];

__device__ __forceinline__ float to_tf32(float x) {
    uint32_t y;
    asm("cvt.rna.tf32.f32 %0, %1;" : "=r"(y) : "f"(x));
    return __uint_as_float(y);
}

__device__ __forceinline__ void mma8(float* d, const uint32_t* a, const uint32_t* b) {
    asm volatile(
        "mma.sync.aligned.m16n8k8.row.col.f32.tf32.tf32.f32 "
        "{%0,%1,%2,%3},{%4,%5,%6,%7},{%8,%9},{%0,%1,%2,%3};"
        : "+f"(d[0]), "+f"(d[1]), "+f"(d[2]), "+f"(d[3])
        : "r"(a[0]), "r"(a[1]), "r"(a[2]), "r"(a[3]), "r"(b[0]), "r"(b[1]));
}

// ---------------------------------------------------------------------------
// Projection (fp32): Y[b][e][j] = sum_c W[c][e]*X[b][c][j] + bias
// ---------------------------------------------------------------------------
__global__ __launch_bounds__(256) void proj_kernel(
    const float* __restrict__ X, const float* __restrict__ W,
    const float* __restrict__ bias, float* __restrict__ Y) {
    __shared__ float As[16][64];
    __shared__ float Xs[16][64];
    const int tid = threadIdx.x;
    const int tx = tid & 15, ty = tid >> 4;
    const int j0 = blockIdx.x * 64;
    const int e0 = blockIdx.y * 64;
    const size_t xoff = (size_t)blockIdx.z * CC * NJ;

    float acc[4][4] = {};
    for (int c0 = 0; c0 < CC; c0 += 16) {
#pragma unroll
        for (int i = 0; i < 4; i++) {
            int idx = tid + i * 256;
            int kk = idx >> 6, l = idx & 63;
            As[kk][l] = W[(size_t)(c0 + kk) * CC + e0 + l];
            Xs[kk][l] = X[xoff + (size_t)(c0 + kk) * NJ + j0 + l];
        }
        __syncthreads();
#pragma unroll
        for (int kk = 0; kk < 16; kk++) {
            float4 a4 = *(const float4*)&As[kk][ty * 4];
            float4 x4 = *(const float4*)&Xs[kk][tx * 4];
            float av[4] = {a4.x, a4.y, a4.z, a4.w};
            float xv[4] = {x4.x, x4.y, x4.z, x4.w};
#pragma unroll
            for (int i = 0; i < 4; i++)
#pragma unroll
                for (int j = 0; j < 4; j++)
                    acc[i][j] = fmaf(av[i], xv[j], acc[i][j]);
        }
        __syncthreads();
    }

    const int d = j0 >> 11;
#pragma unroll
    for (int i = 0; i < 4; i++) {
        int e = e0 + ty * 4 + i;
        float b0 = bias[e * 3 + 0], b1 = bias[e * 3 + 1], b2 = bias[e * 3 + 2];
        float u = 1e-6f * bias[e * 3 + d] * rsqrtf(b0 * b0 + b1 * b1 + b2 * b2);
#pragma unroll
        for (int j = 0; j < 4; j++)
            Y[xoff + (size_t)e * NJ + j0 + tx * 4 + j] = acc[i][j] + u;
    }
}

// ---------------------------------------------------------------------------
// TF32 tensor-core flash attention.
// Block = 8 warps; warp w owns m-rows [w*16, w*16+16). q A-frags persistent.
// Per n-tile(64): S = q^T k (mma), online softmax on c-frags, P via per-warp
// smem -> a-frags, O += P @ z^T (mma).
// ---------------------------------------------------------------------------
__global__ __launch_bounds__(256, 1) void flash_kernel() {
    extern __shared__ float sm[];
    float* ks = sm + KS_OFF;       // [64][KSTR]
    float* zs = sm + ZS_OFF;       // [96][ZSTR2]
    float* qstage = sm;            // prologue alias [96][QSTR]

    const int tid = threadIdx.x;
    const int warp = tid >> 5;
    const int lane = tid & 31;
    const int qr = lane >> 2;      // 0..7
    const int qc = lane & 3;       // 0..3
    float* pw = sm + PS_OFF + warp * (16 * PSTR);

    const int m0 = blockIdx.x * MT;
    const size_t base = ((size_t)blockIdx.z * ROWS + (size_t)blockIdx.y * KF) * NN;
    const float* qg = g_q + base;
    const float* kg = g_k + base;
    const float* zg = g_z + base;

    // ---- prologue: stage q tile [96][128], build persistent A-frags ----
#pragma unroll
    for (int i = 0; i < 48; i++) {
        int idx = tid + i * 256;
        int k = idx >> 7, m = idx & 127;
        qstage[k * QSTR + m] = to_tf32(qg[(size_t)k * NN + m0 + m]);
    }
    __syncthreads();

    uint32_t aq[12][4];
    {
        const int ml = warp * 16 + qr;
#pragma unroll
        for (int kk = 0; kk < 12; kk++) {
            int k = kk * 8 + qc;
            aq[kk][0] = __float_as_uint(qstage[k * QSTR + ml]);
            aq[kk][1] = __float_as_uint(qstage[k * QSTR + ml + 8]);
            aq[kk][2] = __float_as_uint(qstage[(k + 4) * QSTR + ml]);
            aq[kk][3] = __float_as_uint(qstage[(k + 4) * QSTR + ml + 8]);
        }
    }

    float o[12][4] = {};
    float m_0 = -INFINITY, m_1 = -INFINITY, l_0 = 0.f, l_1 = 0.f;
    const float C2 = 0.10206207261596577f * 1.4426950408889634f;  // scale*log2(e)

    for (int nt = 0; nt < 32; nt++) {
        __syncthreads();  // prev PV done (and prologue frag reads on iter 0)
        const int n0 = nt * NT;
#pragma unroll
        for (int i = 0; i < 24; i++) {
            int idx = tid + i * 256;
            int k = idx >> 6, n = idx & 63;
            ks[n * KSTR + k]  = to_tf32(kg[(size_t)k * NN + n0 + n]);
            zs[k * ZSTR2 + n] = to_tf32(zg[(size_t)k * NN + n0 + n]);
        }
        __syncthreads();

        // ---- S = q^T k ----
        float s[8][4] = {};
#pragma unroll
        for (int kk = 0; kk < 12; kk++) {
#pragma unroll
            for (int j = 0; j < 8; j++) {
                const float* kp = &ks[(j * 8 + qr) * KSTR + kk * 8 + qc];
                uint32_t b[2];
                b[0] = __float_as_uint(kp[0]);
                b[1] = __float_as_uint(kp[4]);
                mma8(s[j], aq[kk], b);
            }
        }

        // ---- online softmax (rows qr and qr+8; reduce across quad) ----
        float rm0 = -INFINITY, rm1 = -INFINITY;
#pragma unroll
        for (int j = 0; j < 8; j++) {
            rm0 = fmaxf(rm0, fmaxf(s[j][0], s[j][1]));
            rm1 = fmaxf(rm1, fmaxf(s[j][2], s[j][3]));
        }
        rm0 = fmaxf(rm0, __shfl_xor_sync(0xffffffffu, rm0, 1));
        rm0 = fmaxf(rm0, __shfl_xor_sync(0xffffffffu, rm0, 2));
        rm1 = fmaxf(rm1, __shfl_xor_sync(0xffffffffu, rm1, 1));
        rm1 = fmaxf(rm1, __shfl_xor_sync(0xffffffffu, rm1, 2));

        float mn0 = fmaxf(m_0, rm0), mn1 = fmaxf(m_1, rm1);
        float corr0 = exp2f((m_0 - mn0) * C2);
        float corr1 = exp2f((m_1 - mn1) * C2);
        m_0 = mn0; m_1 = mn1;

        float rs0 = 0.f, rs1 = 0.f;
#pragma unroll
        for (int j = 0; j < 8; j++) {
            s[j][0] = exp2f((s[j][0] - mn0) * C2);
            s[j][1] = exp2f((s[j][1] - mn0) * C2);
            s[j][2] = exp2f((s[j][2] - mn1) * C2);
            s[j][3] = exp2f((s[j][3] - mn1) * C2);
            rs0 += s[j][0] + s[j][1];
            rs1 += s[j][2] + s[j][3];
        }
        rs0 += __shfl_xor_sync(0xffffffffu, rs0, 1);
        rs0 += __shfl_xor_sync(0xffffffffu, rs0, 2);
        rs1 += __shfl_xor_sync(0xffffffffu, rs1, 1);
        rs1 += __shfl_xor_sync(0xffffffffu, rs1, 2);
        l_0 = l_0 * corr0 + rs0;
        l_1 = l_1 * corr1 + rs1;
#pragma unroll
        for (int jp = 0; jp < 12; jp++) {
            o[jp][0] *= corr0; o[jp][1] *= corr0;
            o[jp][2] *= corr1; o[jp][3] *= corr1;
        }

        // ---- P: c-frag -> per-warp smem -> a-frag ----
#pragma unroll
        for (int j = 0; j < 8; j++) {
            *(float2*)&pw[qr * PSTR + j * 8 + 2 * qc]       = make_float2(s[j][0], s[j][1]);
            *(float2*)&pw[(qr + 8) * PSTR + j * 8 + 2 * qc] = make_float2(s[j][2], s[j][3]);
        }
        __syncwarp();

        uint32_t ap[8][4];
#pragma unroll
        for (int c = 0; c < 8; c++) {
            ap[c][0] = __float_as_uint(pw[qr * PSTR + c * 8 + qc]);
            ap[c][1] = __float_as_uint(pw[(qr + 8) * PSTR + c * 8 + qc]);
            ap[c][2] = __float_as_uint(pw[qr * PSTR + c * 8 + qc + 4]);
            ap[c][3] = __float_as_uint(pw[(qr + 8) * PSTR + c * 8 + qc + 4]);
        }

        // ---- O += P @ z^T ----
#pragma unroll
        for (int c = 0; c < 8; c++) {
#pragma unroll
            for (int jp = 0; jp < 12; jp++) {
                const float* zp = &zs[(jp * 8 + qr) * ZSTR2 + c * 8 + qc];
                uint32_t b[2];
                b[0] = __float_as_uint(zp[0]);
                b[1] = __float_as_uint(zp[4]);
                mma8(o[jp], ap[c], b);
            }
        }
    }

    // ---- epilogue: normalize, write [k'][m] ----
    float* og = g_o + base;
    const int mg0 = m0 + warp * 16 + qr;
    const float inv0 = 1.f / l_0, inv1 = 1.f / l_1;
#pragma unroll
    for (int jp = 0; jp < 12; jp++) {
        int c = jp * 8 + 2 * qc;
        og[(size_t)c * NN + mg0]           = o[jp][0] * inv0;
        og[(size_t)(c + 1) * NN + mg0]     = o[jp][1] * inv0;
        og[(size_t)c * NN + mg0 + 8]       = o[jp][2] * inv1;
        og[(size_t)(c + 1) * NN + mg0 + 8] = o[jp][3] * inv1;
    }
}

// ---------------------------------------------------------------------------
extern "C" void kernel_launch(void* const* d_in, const int* in_sizes, int n_in,
                              void* d_out, int out_size) {
    const float* Q  = (const float*)d_in[0];
    const float* K  = (const float*)d_in[1];
    const float* Z  = (const float*)d_in[2];
    const float* Wq = (const float*)d_in[3];
    const float* bq = (const float*)d_in[4];
    const float* Wk = (const float*)d_in[5];
    const float* bk = (const float*)d_in[6];
    const float* Wz = (const float*)d_in[7];
    const float* bz = (const float*)d_in[8];
    const float* Wo = (const float*)d_in[9];
    const float* bo = (const float*)d_in[10];
    float* out = (float*)d_out;

    float *pq, *pk, *pz, *po;
    cudaGetSymbolAddress((void**)&pq, g_q);
    cudaGetSymbolAddress((void**)&pk, g_k);
    cudaGetSymbolAddress((void**)&pz, g_z);
    cudaGetSymbolAddress((void**)&po, g_o);

    const int FLASH_SMEM = SMEM_FLOATS * 4;  // 86528 B
    cudaFuncSetAttribute(flash_kernel,
                         cudaFuncAttributeMaxDynamicSharedMemorySize, FLASH_SMEM);

    dim3 blk(256);
    dim3 gproj(NJ / 64, CC / 64, BB);
    proj_kernel<<<gproj, blk>>>(Q, Wq, bq, pq);
    proj_kernel<<<gproj, blk>>>(K, Wk, bk, pk);
    proj_kernel<<<gproj, blk>>>(Z, Wz, bz, pz);

    flash_kernel<<<dim3(NN / MT, HH, BB), blk, FLASH_SMEM>>>();

    proj_kernel<<<gproj, blk>>>(po, Wo, bo, out);
}